// round 2
// baseline (speedup 1.0000x reference)
#include <cuda_runtime.h>

// SoftDTW-style scan, column-split across CTAs.
//
// out[b,0,:] = x[b,0,:]
// out[b,t,j] = x[b,t,j] + soft(out[b,t-1,j], out[b,t-1,j-1]),
//   soft(a,bb) = bb + d*sigmoid(d), d = a-bb;  global column 0 uses 'a'.
//
// Parallelization: the step recurrence couples column j only to j-1, so each
// batch's 2048 columns are split into CSPLIT=4 chunks, one CTA each
// (32*4 = 128 CTAs, all co-resident on 148 SMs -> spin-wait is safe).
// Cross-CTA dependency = one float per step (the left chunk's rightmost
// column), which the producer already writes to `out`. Producers publish a
// progress flag every BSTEP steps; consumers spin, then bulk-read the BSTEP
// boundary values from `out` via __ldcg (L2). Pipeline fill = 3 blocks.
//
// Intra-CTA: 256 threads, 2 adjacent columns each (float2). Left-neighbor
// exchange via __shfl_up within warps; only 8 warp-boundary values go through
// (double-buffered) smem + one __syncthreads per step. x rows are register-
// prefetched PF=8 steps ahead to cover DRAM latency.

#define SEQ_T  1024
#define COLS   2048
#define NBATCH 32
#define CSPLIT 4
#define CHUNK  (COLS / CSPLIT)   // 512
#define NT     (CHUNK / 2)       // 256 threads
#define NWARP  (NT / 32)         // 8
#define BSTEP  16
#define PF     8

__device__ int g_progress[NBATCH * CSPLIT];

__global__ __launch_bounds__(NT, 1)
void softdtw_split_kernel(const float* __restrict__ x, float* __restrict__ out)
{
    __shared__ float wbuf[2][NWARP];
    __shared__ float lefts_s[BSTEP];

    const int b    = blockIdx.x / CSPLIT;
    const int k    = blockIdx.x % CSPLIT;
    const int tid  = threadIdx.x;
    const int warp = tid >> 5;
    const int lane = tid & 31;

    const int    cs      = k * CHUNK;
    const size_t rowbase = (size_t)b * SEQ_T * COLS;
    const float* xb = x   + rowbase + cs + 2 * tid;
    float*       ob = out + rowbase + cs + 2 * tid;
    const float* leftcol = out + rowbase + cs - 1;   // + t*COLS

    int* myflag   = &g_progress[b * CSPLIT + k];
    int* leftflag = &g_progress[b * CSPLIT + k - 1];

    // t = 0: carry = x row 0, emit it.
    float2 cr = __ldg((const float2*)xb);
    *(float2*)ob = cr;
    float c0 = cr.x, c1 = cr.y;

    // Rolling register prefetch of x rows 1..PF.
    float2 xf[PF];
#pragma unroll
    for (int i = 0; i < PF; i++)
        xf[i] = __ldg((const float2*)(xb + (size_t)(1 + i) * COLS));

    const int nblocks = (SEQ_T - 1 + BSTEP - 1) / BSTEP;  // 64 (last is 15 steps)

    for (int blk = 0; blk < nblocks; blk++) {
        const int t0     = 1 + blk * BSTEP;
        const int nsteps = min(BSTEP, SEQ_T - t0);

        if (k > 0) {
            if (tid == 0) {
                while (*((volatile int*)leftflag) < blk + 1) { }
            }
            __syncthreads();   // flag satisfied -> left rows are in L2
            if (tid < nsteps)
                lefts_s[tid] = __ldcg(leftcol + (size_t)(t0 - 1 + tid) * COLS);
        }
        __syncthreads();       // lefts_s visible (and block-aligned for k==0)

#pragma unroll
        for (int j = 0; j < BSTEP; j++) {
            const int tt = t0 + j;
            if (tt < SEQ_T) {                 // uniform across the block
                const int par = tt & 1;

                // Boundary exchange: my col0's left is previous thread's c1.
                float lv = __shfl_up_sync(0xffffffffu, c1, 1);
                if (lane == 31) wbuf[par][warp] = c1;
                __syncthreads();
                if (lane == 0)
                    lv = (warp > 0) ? wbuf[par][warp - 1]
                                    : (k > 0 ? lefts_s[j] : 0.0f);

                const int   slot = (tt - 1) & (PF - 1);
                const float2 xv  = xf[slot];
                if (tt + PF < SEQ_T)
                    xf[slot] = __ldg((const float2*)(xb + (size_t)(tt + PF) * COLS));

                // Element 0: a = c0, b = lv
                float d0 = c0 - lv;
                float p0 = __fdividef(1.0f, 1.0f + __expf(-d0));
                float s0 = fmaf(d0, p0, lv);
                if (k == 0 && tid == 0) s0 = c0;   // global column 0

                // Element 1: a = c1, b = c0 (previous step's value)
                float d1 = c1 - c0;
                float p1 = __fdividef(1.0f, 1.0f + __expf(-d1));
                float s1 = fmaf(d1, p1, c0);

                c0 = s0 + xv.x;
                c1 = s1 + xv.y;
                *(float2*)(ob + (size_t)tt * COLS) = make_float2(c0, c1);
            }
        }

        if (k < CSPLIT - 1) {
            __threadfence();        // my block's STGs -> GPU scope
            __syncthreads();        // everyone's fence done
            if (tid == 0) atomicExch(myflag, blk + 1);
        }
    }
}

extern "C" void kernel_launch(void* const* d_in, const int* in_sizes, int n_in,
                              void* d_out, int out_size)
{
    (void)in_sizes; (void)n_in; (void)out_size;
    const float* x = (const float*)d_in[0];
    float*       o = (float*)d_out;

    void* pflag = nullptr;
    cudaGetSymbolAddress(&pflag, g_progress);
    cudaMemsetAsync(pflag, 0, sizeof(int) * NBATCH * CSPLIT);

    softdtw_split_kernel<<<NBATCH * CSPLIT, NT>>>(x, o);
}

// round 3
// speedup vs baseline: 2.1393x; 2.1393x over previous
#include <cuda_runtime.h>

// SoftDTW-style scan: out[b,0,:] = x[b,0,:]
// out[b,t,j] = x[b,t,j] + soft(out[b,t-1,j], out[b,t-1,j-1])
//   soft(a,bb) = bb + d*sigmoid(d), d = a-bb;  global column 0 keeps 'a'.
//
// 1 CTA per batch, 512 threads, 4 adjacent columns per thread (registers).
// Per step: the only cross-thread value is each thread's rightmost column ->
// right neighbor: shfl_up within warps, smem (double-buffered, 1 BAR/step)
// across the 16 warp boundaries. sigmoid computed with a single MUFU op:
// sigmoid(d) = 0.5 + 0.5*tanh(d/2). x rows are register-prefetched with
// compile-time slot indices (unroll-by-3; 1023 = 3*341) to keep the prefetch
// array in registers.

#define SEQ_T 1024
#define COLS  2048
#define NT    512
#define CPT   4
#define NWARP (NT / 32)
#define PF    3

__device__ __forceinline__ float tanh_fast(float v)
{
    float r;
    asm("tanh.approx.f32 %0, %1;" : "=f"(r) : "f"(v));
    return r;
}

// soft(a, bb) = bb + d * sigmoid(d), d = a - bb
__device__ __forceinline__ float softstep(float a, float bb)
{
    float d = a - bb;
    float p = fmaf(0.5f, tanh_fast(0.5f * d), 0.5f);
    return fmaf(d, p, bb);
}

__global__ __launch_bounds__(NT, 1)
void softdtw_scan_kernel(const float* __restrict__ x, float* __restrict__ out)
{
    __shared__ float wbuf[2][NWARP];

    const int b    = blockIdx.x;
    const int tid  = threadIdx.x;
    const int warp = tid >> 5;
    const int lane = tid & 31;

    const size_t base = (size_t)b * SEQ_T * COLS + (size_t)tid * CPT;
    const float* xb = x + base;
    float*       ob = out + base;

    // t = 0: carry = x row 0, emit it.
    float4 cr = __ldg((const float4*)xb);
    *(float4*)ob = cr;
    float c0 = cr.x, c1 = cr.y, c2 = cr.z, c3 = cr.w;

    // Register prefetch of x rows 1..PF (static indices only).
    float4 xf[PF];
#pragma unroll
    for (int i = 0; i < PF; i++)
        xf[i] = __ldg((const float4*)(xb + (size_t)(1 + i) * COLS));

    for (int t = 1; t < SEQ_T; t += PF) {
#pragma unroll
        for (int i = 0; i < PF; i++) {
            const int tt  = t + i;
            const int par = tt & 1;

            // Right column -> right neighbor.
            float lv = __shfl_up_sync(0xffffffffu, c3, 1);
            if (lane == 31) wbuf[par][warp] = c3;
            __syncthreads();
            if (lane == 0 && warp > 0) lv = wbuf[par][warp - 1];

            const float4 xv = xf[i];
            if (tt + PF < SEQ_T)
                xf[i] = __ldg((const float4*)(xb + (size_t)(tt + PF) * COLS));

            float s0 = softstep(c0, lv);
            float s1 = softstep(c1, c0);
            float s2 = softstep(c2, c1);
            float s3 = softstep(c3, c2);
            if (tid == 0) s0 = c0;          // global column 0: keep 'a'

            c0 = s0 + xv.x;
            c1 = s1 + xv.y;
            c2 = s2 + xv.z;
            c3 = s3 + xv.w;

            *(float4*)(ob + (size_t)tt * COLS) = make_float4(c0, c1, c2, c3);
        }
    }
}

extern "C" void kernel_launch(void* const* d_in, const int* in_sizes, int n_in,
                              void* d_out, int out_size)
{
    (void)in_sizes; (void)n_in; (void)out_size;
    const float* x = (const float*)d_in[0];
    float*       o = (float*)d_out;
    softdtw_scan_kernel<<<32, NT>>>(x, o);
}